// round 3
// baseline (speedup 1.0000x reference)
#include <cuda_runtime.h>
#include <cuda_bf16.h>
#include <math.h>

// Problem constants
#define BB   128
#define RR   36
#define VIS  2048
#define MMD  1024
#define EE   512
#define ATT  512
#define DD   1024
#define VV   10000
#define TT   19          // max_len - 1
#define G4   4096        // 4*D
#define KCAT 3072        // VIS + D (packed weight K)

// -------------------- device scratch (no allocs allowed) --------------------
__device__ float g_att_fea[BB * RR * ATT];        // [b*36+r][512]
__device__ float g_WG[TT * BB * G4];              // word-part gates + biases, [t*128+b][4096]
__device__ float g_Wcat[G4 * KCAT];               // [Wih_vis | Whh] packed, [4096][3072]
__device__ float g_bcomb[G4];                     // bih + bhh
__device__ float g_xcat[BB * KCAT];               // [feas(2048) | h(1024)] per batch row
__device__ float g_h[BB * DD];
__device__ float g_c[BB * DD];
__device__ float g_Hout[TT * BB * DD];            // raw h_new per step (masking applied at output)
__device__ float g_gpart[4 * BB * G4];            // split-K partials of gates GEMM
__device__ float g_ahpart[4 * BB * ATT];          // split-K partials of ah GEMM
__device__ int   g_wg_gather[TT * BB];            // embed row gather for WG GEMM

// ---------------------------------------------------------------------------
// Generic tiled SGEMM:  C[M,N] = A[M,K-chunk] @ B[N,:]^T  (B row-major [N,ldb])
// MODE 0: plain (+bias if non-null); split-K via gridDim.z (C += z*M*N)
// MODE 1: A rows gathered through gidx
// MODE 2: decoder output epilogue: row m=(t*128+b) -> out[(b*19+t)*N+n],
//         +bias, zeroed when t >= lens[b]
// ---------------------------------------------------------------------------
template<int BM, int BN, int BK, int TM, int TN, int MODE>
__global__ __launch_bounds__((BM/TM)*(BN/TN))
void gemm_k(const float* __restrict__ A, const float* __restrict__ Bw,
            const float* __restrict__ bias, float* __restrict__ C,
            int M, int N, int lda, int ldb, int kChunk,
            const int* __restrict__ gidx, const int* __restrict__ lens)
{
    constexpr int THREADS = (BM/TM)*(BN/TN);
    constexpr int VW  = (BM*BK)/THREADS;   // floats loaded per thread per tile
    constexpr int TPR = BK/VW;             // threads per tile row
    static_assert(BM == BN, "square tiles assumed");
    static_assert(VW == 4 || VW == 2, "vector width");

    __shared__ float As[BK][BM + 4];
    __shared__ float Bs[BK][BN + 4];

    const int tid  = threadIdx.x;
    const int bm   = blockIdx.y * BM;
    const int bn   = blockIdx.x * BN;
    const int z    = blockIdx.z;
    const int k0   = z * kChunk;
    const int tc   = tid % (BN/TN);
    const int tr   = tid / (BN/TN);
    const int aRow = tid / TPR;
    const int aCol = (tid % TPR) * VW;

    const float* Arow;
    if (MODE == 1) Arow = A + (size_t)gidx[bm + aRow] * lda;
    else           Arow = A + (size_t)(bm + aRow) * lda;
    const int brow  = bn + aRow;
    const bool bok  = (brow < N);
    const float* Brow = Bw + (size_t)(bok ? brow : 0) * ldb;

    float acc[TM][TN];
    #pragma unroll
    for (int i = 0; i < TM; i++)
        #pragma unroll
        for (int j = 0; j < TN; j++) acc[i][j] = 0.f;

    for (int kk = k0; kk < k0 + kChunk; kk += BK) {
        if (VW == 4) {
            float4 av = *(const float4*)(Arow + kk + aCol);
            As[aCol+0][aRow] = av.x; As[aCol+1][aRow] = av.y;
            As[aCol+2][aRow] = av.z; As[aCol+3][aRow] = av.w;
            float4 bv = bok ? *(const float4*)(Brow + kk + aCol)
                            : make_float4(0.f, 0.f, 0.f, 0.f);
            Bs[aCol+0][aRow] = bv.x; Bs[aCol+1][aRow] = bv.y;
            Bs[aCol+2][aRow] = bv.z; Bs[aCol+3][aRow] = bv.w;
        } else {
            float2 av = *(const float2*)(Arow + kk + aCol);
            As[aCol+0][aRow] = av.x; As[aCol+1][aRow] = av.y;
            float2 bv = bok ? *(const float2*)(Brow + kk + aCol)
                            : make_float2(0.f, 0.f);
            Bs[aCol+0][aRow] = bv.x; Bs[aCol+1][aRow] = bv.y;
        }
        __syncthreads();
        #pragma unroll
        for (int k = 0; k < BK; k++) {
            float ra[TM], rb[TN];
            #pragma unroll
            for (int i = 0; i < TM; i++) ra[i] = As[k][tr*TM + i];
            #pragma unroll
            for (int j = 0; j < TN; j++) rb[j] = Bs[k][tc*TN + j];
            #pragma unroll
            for (int i = 0; i < TM; i++)
                #pragma unroll
                for (int j = 0; j < TN; j++) acc[i][j] += ra[i]*rb[j];
        }
        __syncthreads();
    }

    float* Cz = C + (size_t)z * M * N;
    #pragma unroll
    for (int i = 0; i < TM; i++) {
        int m = bm + tr*TM + i;
        size_t rowoff;
        bool msk = true;
        if (MODE == 2) {
            int t = m >> 7, b = m & 127;
            msk = (t < lens[b]);
            rowoff = (size_t)(b * TT + t) * N;
        } else {
            rowoff = (size_t)m * N;
        }
        #pragma unroll
        for (int j = 0; j < TN; j++) {
            int n = bn + tc*TN + j;
            if (n < N) {
                float v = acc[i][j];
                if (bias) v += bias[n];
                if (MODE == 2 && !msk) v = 0.f;
                Cz[rowoff + n] = v;
            }
        }
    }
}

// ---------------- pack [Wih_vis | Whh] and combined bias --------------------
__global__ void pack_kernel(const float* __restrict__ Wih, const float* __restrict__ Whh,
                            const float* __restrict__ bih, const float* __restrict__ bhh)
{
    int idx = blockIdx.x * blockDim.x + threadIdx.x;
    if (idx < G4 * KCAT) {
        int g = idx / KCAT, k = idx % KCAT;
        g_Wcat[idx] = (k < VIS) ? Wih[(size_t)g * (VIS+EE) + k]
                                : Whh[(size_t)g * DD + (k - VIS)];
    }
    if (idx < G4) g_bcomb[idx] = bih[idx] + bhh[idx];
}

// ---------------- gather indices for word-gates GEMM ------------------------
__global__ void build_gather(const int* __restrict__ captions)
{
    int m = blockIdx.x * blockDim.x + threadIdx.x;
    if (m < TT * BB) {
        int t = m >> 7, b = m & 127;
        g_wg_gather[m] = captions[b * (TT + 1) + t];
    }
}

// ---------------- copy h0 into xcat recurrent slot --------------------------
__global__ void copy_h_xcat()
{
    int idx = blockIdx.x * blockDim.x + threadIdx.x;   // 131072
    int b = idx >> 10, d = idx & 1023;
    g_xcat[b * KCAT + VIS + d] = g_h[idx];
}

// ---------------- attention: scores -> softmax -> context -------------------
// one block per batch element; reads split-K partials of ah = h @ Wh^T
__global__ void attn_kernel(const float* __restrict__ visual,
                            const float* __restrict__ att_bias,
                            const float* __restrict__ Ww, int t)
{
    int b = blockIdx.x;
    __shared__ float ah_s[ATT];
    __shared__ float ww_s[ATT];
    __shared__ float sc_s[RR];
    __shared__ float alpha_s[RR];
    int tid = threadIdx.x, lane = tid & 31, warp = tid >> 5;   // 256 thr, 8 warps

    for (int a = tid; a < ATT; a += 256) {
        float s = g_ahpart[b*ATT + a]
                + g_ahpart[1*BB*ATT + b*ATT + a]
                + g_ahpart[2*BB*ATT + b*ATT + a]
                + g_ahpart[3*BB*ATT + b*ATT + a];
        ah_s[a] = s;
        ww_s[a] = Ww[a];
    }
    __syncthreads();

    for (int r = warp; r < RR; r += 8) {
        const float* af = g_att_fea + ((size_t)b * RR + r) * ATT;
        float ab = att_bias[r];
        float s = 0.f;
        for (int a = lane; a < ATT; a += 32) {
            float v = af[a] + ah_s[a] + ab;
            s += fmaxf(v, 0.f) * ww_s[a];
        }
        #pragma unroll
        for (int o = 16; o > 0; o >>= 1) s += __shfl_xor_sync(0xffffffffu, s, o);
        if (lane == 0) sc_s[r] = s;
    }
    __syncthreads();

    if (tid == 0) {
        float mx = -1e30f;
        for (int r = 0; r < RR; r++) mx = fmaxf(mx, sc_s[r]);
        float sum = 0.f;
        for (int r = 0; r < RR; r++) { float e = expf(sc_s[r] - mx); alpha_s[r] = e; sum += e; }
        float inv = 1.f / sum;
        for (int r = 0; r < RR; r++)
            alpha_s[r] = (t == 0) ? (1.f / (float)RR) : alpha_s[r] * inv;
    }
    __syncthreads();

    float al[RR];
    #pragma unroll
    for (int r = 0; r < RR; r++) al[r] = alpha_s[r];
    const float* vb = visual + (size_t)b * RR * VIS;
    for (int v = tid; v < VIS; v += 256) {
        float s = 0.f;
        #pragma unroll
        for (int r = 0; r < RR; r++) s += al[r] * vb[(size_t)r * VIS + v];
        g_xcat[b * KCAT + v] = s;
    }
}

// ---------------- fused gate-sum + LSTM cell + state writeback --------------
__global__ void lstm_kernel(const int* __restrict__ lens, int t)
{
    int idx = blockIdx.x * blockDim.x + threadIdx.x;   // 131072
    int b = idx >> 10, d = idx & 1023;
    const float* wg = g_WG + ((size_t)t * BB + b) * G4;
    float gi = wg[d], gf = wg[DD + d], gg = wg[2*DD + d], go = wg[3*DD + d];
    #pragma unroll
    for (int s = 0; s < 4; s++) {
        const float* gp = g_gpart + (size_t)s * BB * G4 + (size_t)b * G4;
        gi += gp[d]; gf += gp[DD + d]; gg += gp[2*DD + d]; go += gp[3*DD + d];
    }
    float c  = g_c[idx];
    float i_ = 1.f / (1.f + expf(-gi));
    float f_ = 1.f / (1.f + expf(-gf));
    float g_ = tanhf(gg);
    float o_ = 1.f / (1.f + expf(-go));
    float cn = f_ * c + i_ * g_;
    float hn = o_ * tanhf(cn);
    bool msk = t < lens[b];
    float hw = msk ? hn : g_h[idx];
    float cw = msk ? cn : c;
    g_h[idx] = hw;
    g_c[idx] = cw;
    g_xcat[b * KCAT + VIS + d] = hw;
    g_Hout[(size_t)(t * BB + b) * DD + d] = hn;   // masked at final projection
}

// ---------------------------------------------------------------------------
static float* sym_addr(const void* sym)
{
    void* p = nullptr;
    cudaGetSymbolAddress(&p, sym);
    return (float*)p;
}

extern "C" void kernel_launch(void* const* d_in, const int* in_sizes, int n_in,
                              void* d_out, int out_size)
{
    const float* visual   = (const float*)d_in[0];
    const float* joint    = (const float*)d_in[1];
    const int*   captions = (const int*)  d_in[2];
    const int*   lengths  = (const int*)  d_in[3];
    // d_in[4] = max_len (constant 20, hardcoded)
    const float* embed_W  = (const float*)d_in[5];
    const float* Wih      = (const float*)d_in[6];
    const float* bih      = (const float*)d_in[7];
    const float* Whh      = (const float*)d_in[8];
    const float* bhh      = (const float*)d_in[9];
    const float* W_init_h = (const float*)d_in[10];
    const float* b_init_h = (const float*)d_in[11];
    const float* W_init_c = (const float*)d_in[12];
    const float* b_init_c = (const float*)d_in[13];
    const float* Wv       = (const float*)d_in[14];
    const float* Wh       = (const float*)d_in[15];
    const float* att_bias = (const float*)d_in[16];
    const float* Ww       = (const float*)d_in[17];
    const float* Wout     = (const float*)d_in[18];
    const float* bout     = (const float*)d_in[19];
    float* out = (float*)d_out;

    float* p_attfea = sym_addr(g_att_fea);
    float* p_WG     = sym_addr(g_WG);
    float* p_bcomb  = sym_addr(g_bcomb);
    float* p_xcat   = sym_addr(g_xcat);
    float* p_h      = sym_addr(g_h);
    float* p_c      = sym_addr(g_c);
    float* p_Hout   = sym_addr(g_Hout);
    float* p_gpart  = sym_addr(g_gpart);
    float* p_ahpart = sym_addr(g_ahpart);
    int*   p_gather = (int*)sym_addr(g_wg_gather);

    // ---- setup (batched precomputes) ----
    pack_kernel<<<(G4*KCAT + 1023)/1024, 1024>>>(Wih, Whh, bih, bhh);
    build_gather<<<3, 1024>>>(captions);

    // att_fea[b,r,:] = visual[b,r,:] @ Wv^T      (M=4608, N=512, K=2048)
    gemm_k<128,128,8,8,8,0><<<dim3(4,36,1), 256>>>(
        visual, Wv, nullptr, p_attfea, BB*RR, ATT, VIS, VIS, VIS, nullptr, nullptr);

    // WG[t,b,:] = embed(captions[b,t]) @ Wih_word^T + bih + bhh  (M=2432, N=4096, K=512)
    gemm_k<128,128,8,8,8,1><<<dim3(32,19,1), 256>>>(
        embed_W, Wih + VIS, p_bcomb, p_WG, TT*BB, G4, EE, VIS+EE, EE, p_gather, nullptr);

    // h0 / c0   (M=128, N=1024, K=1024)
    gemm_k<64,64,8,4,4,0><<<dim3(16,2,1), 256>>>(
        joint, W_init_h, b_init_h, p_h, BB, DD, MMD, MMD, MMD, nullptr, nullptr);
    gemm_k<64,64,8,4,4,0><<<dim3(16,2,1), 256>>>(
        joint, W_init_c, b_init_c, p_c, BB, DD, MMD, MMD, MMD, nullptr, nullptr);
    copy_h_xcat<<<128, 1024>>>();

    // ---- recurrence ----
    for (int t = 0; t < TT; t++) {
        // ah = h @ Wh^T, split-K=4 partials   (M=128, N=512, K=1024)
        gemm_k<64,64,8,4,4,0><<<dim3(8,2,4), 256>>>(
            p_h, Wh, nullptr, p_ahpart, BB, ATT, DD, DD, DD/4, nullptr, nullptr);
        // attention -> writes feas into xcat[:, :2048]
        attn_kernel<<<BB, 256>>>(visual, att_bias, Ww, t);
        // gates partials = xcat @ [Wih_vis|Whh]^T, split-K=4  (M=128, N=4096, K=3072)
        gemm_k<128,128,8,8,8,0><<<dim3(32,1,4), 256>>>(
            p_xcat, sym_addr(g_Wcat), nullptr, p_gpart, BB, G4, KCAT, KCAT, KCAT/4,
            nullptr, nullptr);
        // fused gate sum + LSTM cell + state update
        lstm_kernel<<<128, 1024>>>(lengths, t);
    }

    // ---- batched vocab projection with mask epilogue (M=2432, N=10000, K=1024) ----
    gemm_k<128,128,8,8,8,2><<<dim3(79,19,1), 256>>>(
        p_Hout, Wout, bout, out, TT*BB, VV, DD, DD, DD, nullptr, lengths);

    (void)in_sizes; (void)n_in; (void)out_size;
}

// round 5
// speedup vs baseline: 1.9461x; 1.9461x over previous
#include <cuda_runtime.h>
#include <cuda_bf16.h>
#include <math.h>
#include <stdint.h>

// Problem constants
#define BB   128
#define RR   36
#define VIS  2048
#define MMD  1024
#define EE   512
#define ATT  512
#define DD   1024
#define VV   10000
#define TT   19          // max_len - 1
#define G4   4096        // 4*D
#define KCAT 3072        // VIS + D
#define MW   (TT*BB)     // 2432
#define NSPL 8           // split-K for gates GEMM

// -------------------- device scratch (no allocs allowed) --------------------
__device__ __nv_bfloat16 g_words_hi[MW*EE],   g_words_lo[MW*EE];
__device__ __nv_bfloat16 g_WihW_hi[G4*EE],    g_WihW_lo[G4*EE];
__device__ __nv_bfloat16 g_Wcat_hi[G4*KCAT],  g_Wcat_lo[G4*KCAT];
__device__ __nv_bfloat16 g_Wout_hi[VV*DD],    g_Wout_lo[VV*DD];
__device__ __nv_bfloat16 g_vis_hi[BB*RR*VIS], g_vis_lo[BB*RR*VIS];
__device__ __nv_bfloat16 g_Wv_hi[ATT*VIS],    g_Wv_lo[ATT*VIS];
__device__ __nv_bfloat16 g_Hout_hi[MW*DD],    g_Hout_lo[MW*DD];
__device__ __nv_bfloat16 g_x_hi[BB*KCAT],     g_x_lo[BB*KCAT];
// fp32 scratch
__device__ float g_att_fea[BB*RR*ATT];
__device__ float g_WG[MW*G4];
__device__ float g_bcomb[G4];
__device__ float g_h[BB*DD];
__device__ float g_c[BB*DD];
__device__ float g_gpart[NSPL*BB*G4];
__device__ float g_ahpart[4*BB*ATT];

// ========================= warp-MMA helpers =================================
__device__ __forceinline__ uint32_t smem_u32(const void* p){
    uint32_t a;
    asm("{ .reg .u64 t; cvta.to.shared.u64 t, %1; cvt.u32.u64 %0, t; }" : "=r"(a) : "l"(p));
    return a;
}
__device__ __forceinline__ void ldsm_x4(uint32_t* r, uint32_t addr){
    asm volatile("ldmatrix.sync.aligned.m8n8.x4.shared.b16 {%0,%1,%2,%3}, [%4];"
                 : "=r"(r[0]), "=r"(r[1]), "=r"(r[2]), "=r"(r[3]) : "r"(addr));
}
__device__ __forceinline__ void mma_bf16(float* c, const uint32_t* a, const uint32_t* b){
    asm volatile(
        "mma.sync.aligned.m16n8k16.row.col.f32.bf16.bf16.f32 "
        "{%0,%1,%2,%3}, {%4,%5,%6,%7}, {%8,%9}, {%0,%1,%2,%3};"
        : "+f"(c[0]), "+f"(c[1]), "+f"(c[2]), "+f"(c[3])
        : "r"(a[0]), "r"(a[1]), "r"(a[2]), "r"(a[3]), "r"(b[0]), "r"(b[1]));
}

// ============== split-bf16 warp-MMA GEMM (128x128 block tile) ===============
// C[M,Ntot] = (Ahi+Alo)[M,K] @ (Bhi+Blo)[Ntot,K]^T   (3-term, fp32 accum)
// grid = (ceil(Ntot/128), M/128, splits); kChunk = K/splits
// MODE 0: C at z*M*Ntot offset, optional bias
// MODE 2: decoder out: row m=(t*128+b) -> C[(b*TT+t)*Ntot + n], +bias, mask lens
#define SROW 40   // smem row stride in bf16 (80 bytes)
template<int MODE>
__global__ __launch_bounds__(256, 2)
void tgemm(const __nv_bfloat16* __restrict__ Ahi, const __nv_bfloat16* __restrict__ Alo,
           const __nv_bfloat16* __restrict__ Bhi, const __nv_bfloat16* __restrict__ Blo,
           const float* __restrict__ bias, float* __restrict__ C,
           int M, int Ntot, int K, int kChunk, const int* __restrict__ lens)
{
    __shared__ __align__(16) __nv_bfloat16 sA0[128*SROW], sA1[128*SROW];
    __shared__ __align__(16) __nv_bfloat16 sB0[128*SROW], sB1[128*SROW];

    const int tid = threadIdx.x, wid = tid >> 5, lane = tid & 31;
    const int bm = blockIdx.y * 128, bn = blockIdx.x * 128, z = blockIdx.z;
    const int k0 = z * kChunk;

    const uint32_t uA0 = smem_u32(sA0), uA1 = smem_u32(sA1);
    const uint32_t uB0 = smem_u32(sB0), uB1 = smem_u32(sB1);

    // global load setup: each thread loads 2 rows x 16B per tile per iter
    const int lr  = tid >> 2;              // 0..63
    const int lcg = tid & 3;               // 16B chunk in row
    const uint32_t so0 = (uint32_t)(lr * 80 + lcg * 16);
    const uint32_t so1 = (uint32_t)((lr + 64) * 80 + lcg * 16);
    const size_t gao0 = (size_t)(bm + lr) * K + k0 + lcg * 8;
    const size_t gao1 = gao0 + (size_t)64 * K;
    const bool ok0 = (bn + lr) < Ntot;
    const bool ok1 = (bn + lr + 64) < Ntot;
    const size_t gbo0 = (size_t)(ok0 ? bn + lr : 0) * K + k0 + lcg * 8;
    const size_t gbo1 = (size_t)(ok1 ? bn + lr + 64 : 0) * K + k0 + lcg * 8;

    // ldmatrix per-thread row offsets (bytes)
    const int wm = (wid >> 2) * 64, wn = (wid & 3) * 32;
    const uint32_t aRowOff = (uint32_t)((lane & 15) * 80 + (lane >> 4) * 16);
    const uint32_t bRowOff = (uint32_t)(((lane & 7) + ((lane >> 4) & 1) * 8) * 80
                                        + ((lane >> 3) & 1) * 16);

    float acc[4][4][4];
    #pragma unroll
    for (int mi = 0; mi < 4; mi++)
        #pragma unroll
        for (int ni = 0; ni < 4; ni++)
            #pragma unroll
            for (int q = 0; q < 4; q++) acc[mi][ni][q] = 0.f;

    const int nIter = kChunk / 32;
    for (int it = 0; it < nIter; it++) {
        const size_t koff = (size_t)it * 32;
        __syncthreads();
        *(uint4*)((char*)sA0 + so0) = *(const uint4*)(Ahi + gao0 + koff);
        *(uint4*)((char*)sA0 + so1) = *(const uint4*)(Ahi + gao1 + koff);
        *(uint4*)((char*)sA1 + so0) = *(const uint4*)(Alo + gao0 + koff);
        *(uint4*)((char*)sA1 + so1) = *(const uint4*)(Alo + gao1 + koff);
        uint4 z4 = make_uint4(0,0,0,0);
        *(uint4*)((char*)sB0 + so0) = ok0 ? *(const uint4*)(Bhi + gbo0 + koff) : z4;
        *(uint4*)((char*)sB0 + so1) = ok1 ? *(const uint4*)(Bhi + gbo1 + koff) : z4;
        *(uint4*)((char*)sB1 + so0) = ok0 ? *(const uint4*)(Blo + gbo0 + koff) : z4;
        *(uint4*)((char*)sB1 + so1) = ok1 ? *(const uint4*)(Blo + gbo1 + koff) : z4;
        __syncthreads();

        #pragma unroll
        for (int ks = 0; ks < 2; ks++) {
            const uint32_t kb = ks * 32;   // byte offset of k16 step
            uint32_t bh[4][2], bl[4][2], a[4][4];
            // B hi/lo fragments: 2 x ldmatrix.x4 each (covers 4 n-frags)
            ldsm_x4(&bh[0][0], uB0 + (uint32_t)(wn) * 80 + kb + bRowOff);
            ldsm_x4(&bh[2][0], uB0 + (uint32_t)(wn + 16) * 80 + kb + bRowOff);
            ldsm_x4(&bl[0][0], uB1 + (uint32_t)(wn) * 80 + kb + bRowOff);
            ldsm_x4(&bl[2][0], uB1 + (uint32_t)(wn + 16) * 80 + kb + bRowOff);
            // A hi fragments, then hi x (bhi, blo)
            #pragma unroll
            for (int mi = 0; mi < 4; mi++)
                ldsm_x4(a[mi], uA0 + (uint32_t)(wm + mi * 16) * 80 + kb + aRowOff);
            #pragma unroll
            for (int mi = 0; mi < 4; mi++)
                #pragma unroll
                for (int ni = 0; ni < 4; ni++) {
                    mma_bf16(acc[mi][ni], a[mi], bh[ni]);
                    mma_bf16(acc[mi][ni], a[mi], bl[ni]);
                }
            // A lo fragments (reuse regs), lo x bhi
            #pragma unroll
            for (int mi = 0; mi < 4; mi++)
                ldsm_x4(a[mi], uA1 + (uint32_t)(wm + mi * 16) * 80 + kb + aRowOff);
            #pragma unroll
            for (int mi = 0; mi < 4; mi++)
                #pragma unroll
                for (int ni = 0; ni < 4; ni++)
                    mma_bf16(acc[mi][ni], a[mi], bh[ni]);
        }
    }

    // ------------------------------ epilogue -------------------------------
    float* Cz = C + (size_t)z * M * Ntot;
    const int rbase = lane >> 2;
    const int cbase = 2 * (lane & 3);
    #pragma unroll
    for (int mi = 0; mi < 4; mi++) {
        #pragma unroll
        for (int half = 0; half < 2; half++) {
            const int m = bm + wm + mi * 16 + rbase + half * 8;
            size_t ro;
            bool msk = true;
            if (MODE == 2) {
                const int t = m >> 7, b = m & 127;
                msk = t < lens[b];
                ro = (size_t)(b * TT + t) * Ntot;
            } else {
                ro = (size_t)m * Ntot;
            }
            #pragma unroll
            for (int ni = 0; ni < 4; ni++) {
                const int n = bn + wn + ni * 8 + cbase;
                float v0 = acc[mi][ni][half * 2 + 0];
                float v1 = acc[mi][ni][half * 2 + 1];
                if (MODE == 2) {
                    if (n < Ntot)     Cz[ro + n]     = msk ? v0 + bias[n]     : 0.f;
                    if (n + 1 < Ntot) Cz[ro + n + 1] = msk ? v1 + bias[n + 1] : 0.f;
                } else {
                    if (bias) { v0 += bias[n]; v1 += bias[n + 1]; }
                    if (n < Ntot)     Cz[ro + n]     = v0;
                    if (n + 1 < Ntot) Cz[ro + n + 1] = v1;
                }
            }
        }
    }
}

// =============== small fp32 SGEMM (h0/c0, ah) — 64x64 tiles =================
__global__ __launch_bounds__(256)
void gemm_f32(const float* __restrict__ A, const float* __restrict__ Bw,
              const float* __restrict__ bias, float* __restrict__ C,
              int M, int N, int lda, int ldb, int kChunk)
{
    __shared__ float As[8][68];
    __shared__ float Bs[8][68];
    const int tid = threadIdx.x;
    const int bm = blockIdx.y * 64, bn = blockIdx.x * 64, z = blockIdx.z;
    const int k0 = z * kChunk;
    const int tc = tid % 16, tr = tid / 16;
    const int aRow = tid / 4, aCol = (tid % 4) * 2;
    const float* Arow = A + (size_t)(bm + aRow) * lda;
    const float* Brow = Bw + (size_t)(bn + aRow) * ldb;
    float acc[4][4];
    #pragma unroll
    for (int i = 0; i < 4; i++)
        #pragma unroll
        for (int j = 0; j < 4; j++) acc[i][j] = 0.f;
    for (int kk = k0; kk < k0 + kChunk; kk += 8) {
        float2 av = *(const float2*)(Arow + kk + aCol);
        As[aCol+0][aRow] = av.x; As[aCol+1][aRow] = av.y;
        float2 bv = *(const float2*)(Brow + kk + aCol);
        Bs[aCol+0][aRow] = bv.x; Bs[aCol+1][aRow] = bv.y;
        __syncthreads();
        #pragma unroll
        for (int k = 0; k < 8; k++) {
            float ra[4], rb[4];
            #pragma unroll
            for (int i = 0; i < 4; i++) ra[i] = As[k][tr*4 + i];
            #pragma unroll
            for (int j = 0; j < 4; j++) rb[j] = Bs[k][tc*4 + j];
            #pragma unroll
            for (int i = 0; i < 4; i++)
                #pragma unroll
                for (int j = 0; j < 4; j++) acc[i][j] += ra[i]*rb[j];
        }
        __syncthreads();
    }
    float* Cz = C + (size_t)z * M * N;
    #pragma unroll
    for (int i = 0; i < 4; i++)
        #pragma unroll
        for (int j = 0; j < 4; j++) {
            const int m = bm + tr*4 + i, n = bn + tc*4 + j;
            float v = acc[i][j];
            if (bias) v += bias[n];
            Cz[(size_t)m * N + n] = v;
        }
}

// ======================== conversion / pack kernels =========================
__device__ __forceinline__ void split_store(float x, __nv_bfloat16* hi, __nv_bfloat16* lo, size_t i){
    __nv_bfloat16 h = __float2bfloat16(x);
    hi[i] = h;
    lo[i] = __float2bfloat16(x - __bfloat162float(h));
}
__global__ void split_kernel(const float* __restrict__ src,
                             __nv_bfloat16* __restrict__ hi, __nv_bfloat16* __restrict__ lo,
                             int n)
{
    int i = blockIdx.x * blockDim.x + threadIdx.x;
    if (i < n) split_store(src[i], hi, lo, i);
}
__global__ void pack_split_kernel(const float* __restrict__ Wih, const float* __restrict__ Whh,
                                  const float* __restrict__ bih, const float* __restrict__ bhh)
{
    int idx = blockIdx.x * blockDim.x + threadIdx.x;
    if (idx < G4 * KCAT) {
        int g = idx / KCAT, k = idx % KCAT;
        float x = (k < VIS) ? Wih[(size_t)g * (VIS+EE) + k]
                            : Whh[(size_t)g * DD + (k - VIS)];
        split_store(x, g_Wcat_hi, g_Wcat_lo, idx);
    }
    if (idx < G4) g_bcomb[idx] = bih[idx] + bhh[idx];
}
__global__ void wihw_split_kernel(const float* __restrict__ Wih)
{
    int idx = blockIdx.x * blockDim.x + threadIdx.x;
    if (idx < G4 * EE) {
        int g = idx / EE, k = idx % EE;
        split_store(Wih[(size_t)g * (VIS+EE) + VIS + k], g_WihW_hi, g_WihW_lo, idx);
    }
}
__global__ void words_split_kernel(const int* __restrict__ captions,
                                   const float* __restrict__ embed)
{
    int idx = blockIdx.x * blockDim.x + threadIdx.x;
    if (idx < MW * EE) {
        int m = idx / EE, k = idx % EE;
        int t = m >> 7, b = m & 127;
        int row = captions[b * (TT + 1) + t];
        split_store(embed[(size_t)row * EE + k], g_words_hi, g_words_lo, idx);
    }
}
__global__ void h0_to_x_kernel()
{
    int idx = blockIdx.x * blockDim.x + threadIdx.x;   // BB*DD
    int b = idx >> 10, d = idx & 1023;
    split_store(g_h[idx], g_x_hi, g_x_lo, (size_t)b * KCAT + VIS + d);
}

// =================== attention: scores->softmax->context ====================
__global__ void attn_kernel(const float* __restrict__ visual,
                            const float* __restrict__ att_bias,
                            const float* __restrict__ Ww, int t)
{
    int b = blockIdx.x;
    __shared__ float ah_s[ATT], ww_s[ATT], sc_s[RR], alpha_s[RR];
    int tid = threadIdx.x, lane = tid & 31, warp = tid >> 5;   // 256 thr

    for (int a = tid; a < ATT; a += 256) {
        ah_s[a] = g_ahpart[b*ATT + a] + g_ahpart[1*BB*ATT + b*ATT + a]
                + g_ahpart[2*BB*ATT + b*ATT + a] + g_ahpart[3*BB*ATT + b*ATT + a];
        ww_s[a] = Ww[a];
    }
    __syncthreads();
    for (int r = warp; r < RR; r += 8) {
        const float* af = g_att_fea + ((size_t)b * RR + r) * ATT;
        float ab = att_bias[r], s = 0.f;
        for (int a = lane; a < ATT; a += 32) {
            float v = af[a] + ah_s[a] + ab;
            s += fmaxf(v, 0.f) * ww_s[a];
        }
        #pragma unroll
        for (int o = 16; o > 0; o >>= 1) s += __shfl_xor_sync(0xffffffffu, s, o);
        if (lane == 0) sc_s[r] = s;
    }
    __syncthreads();
    if (tid == 0) {
        float mx = -1e30f;
        for (int r = 0; r < RR; r++) mx = fmaxf(mx, sc_s[r]);
        float sum = 0.f;
        for (int r = 0; r < RR; r++) { float e = expf(sc_s[r] - mx); alpha_s[r] = e; sum += e; }
        float inv = 1.f / sum;
        for (int r = 0; r < RR; r++)
            alpha_s[r] = (t == 0) ? (1.f / (float)RR) : alpha_s[r] * inv;
    }
    __syncthreads();
    float al[RR];
    #pragma unroll
    for (int r = 0; r < RR; r++) al[r] = alpha_s[r];
    const float* vb = visual + (size_t)b * RR * VIS;
    for (int v = tid; v < VIS; v += 256) {
        float s = 0.f;
        #pragma unroll
        for (int r = 0; r < RR; r++) s += al[r] * vb[(size_t)r * VIS + v];
        split_store(s, g_x_hi, g_x_lo, (size_t)b * KCAT + v);
    }
}

// ============== fused gate-sum + LSTM cell + state writeback ================
__global__ void lstm_kernel(const int* __restrict__ lens, int t)
{
    int idx = blockIdx.x * blockDim.x + threadIdx.x;   // BB*DD
    int b = idx >> 10, d = idx & 1023;
    const float* wg = g_WG + ((size_t)t * BB + b) * G4;
    float gi = wg[d], gf = wg[DD + d], gg = wg[2*DD + d], go = wg[3*DD + d];
    #pragma unroll
    for (int s = 0; s < NSPL; s++) {
        const float* gp = g_gpart + (size_t)s * BB * G4 + (size_t)b * G4;
        gi += gp[d]; gf += gp[DD + d]; gg += gp[2*DD + d]; go += gp[3*DD + d];
    }
    float c  = g_c[idx];
    float i_ = 1.f / (1.f + expf(-gi));
    float f_ = 1.f / (1.f + expf(-gf));
    float gt = tanhf(gg);
    float o_ = 1.f / (1.f + expf(-go));
    float cn = f_ * c + i_ * gt;
    float hn = o_ * tanhf(cn);
    bool msk = t < lens[b];
    float hw = msk ? hn : g_h[idx];
    g_h[idx] = hw;
    g_c[idx] = msk ? cn : c;
    split_store(hw, g_x_hi, g_x_lo, (size_t)b * KCAT + VIS + d);
    split_store(hn, g_Hout_hi, g_Hout_lo, (size_t)(t * BB + b) * DD + d);
}

// ---------------------------------------------------------------------------
static void* sym_addr(const void* sym)
{
    void* p = nullptr;
    cudaGetSymbolAddress(&p, sym);
    return p;
}

extern "C" void kernel_launch(void* const* d_in, const int* in_sizes, int n_in,
                              void* d_out, int out_size)
{
    const float* visual   = (const float*)d_in[0];
    const float* joint    = (const float*)d_in[1];
    const int*   captions = (const int*)  d_in[2];
    const int*   lengths  = (const int*)  d_in[3];
    const float* embed_W  = (const float*)d_in[5];
    const float* Wih      = (const float*)d_in[6];
    const float* bih      = (const float*)d_in[7];
    const float* Whh      = (const float*)d_in[8];
    const float* bhh      = (const float*)d_in[9];
    const float* W_init_h = (const float*)d_in[10];
    const float* b_init_h = (const float*)d_in[11];
    const float* W_init_c = (const float*)d_in[12];
    const float* b_init_c = (const float*)d_in[13];
    const float* Wv       = (const float*)d_in[14];
    const float* Wh       = (const float*)d_in[15];
    const float* att_bias = (const float*)d_in[16];
    const float* Ww       = (const float*)d_in[17];
    const float* Wout     = (const float*)d_in[18];
    const float* bout     = (const float*)d_in[19];
    float* out = (float*)d_out;

    __nv_bfloat16* p_words_hi = (__nv_bfloat16*)sym_addr(g_words_hi);
    __nv_bfloat16* p_words_lo = (__nv_bfloat16*)sym_addr(g_words_lo);
    __nv_bfloat16* p_WihW_hi  = (__nv_bfloat16*)sym_addr(g_WihW_hi);
    __nv_bfloat16* p_WihW_lo  = (__nv_bfloat16*)sym_addr(g_WihW_lo);
    __nv_bfloat16* p_Wcat_hi  = (__nv_bfloat16*)sym_addr(g_Wcat_hi);
    __nv_bfloat16* p_Wcat_lo  = (__nv_bfloat16*)sym_addr(g_Wcat_lo);
    __nv_bfloat16* p_Wout_hi  = (__nv_bfloat16*)sym_addr(g_Wout_hi);
    __nv_bfloat16* p_Wout_lo  = (__nv_bfloat16*)sym_addr(g_Wout_lo);
    __nv_bfloat16* p_vis_hi   = (__nv_bfloat16*)sym_addr(g_vis_hi);
    __nv_bfloat16* p_vis_lo   = (__nv_bfloat16*)sym_addr(g_vis_lo);
    __nv_bfloat16* p_Wv_hi    = (__nv_bfloat16*)sym_addr(g_Wv_hi);
    __nv_bfloat16* p_Wv_lo    = (__nv_bfloat16*)sym_addr(g_Wv_lo);
    __nv_bfloat16* p_Hout_hi  = (__nv_bfloat16*)sym_addr(g_Hout_hi);
    __nv_bfloat16* p_Hout_lo  = (__nv_bfloat16*)sym_addr(g_Hout_lo);
    __nv_bfloat16* p_x_hi     = (__nv_bfloat16*)sym_addr(g_x_hi);
    __nv_bfloat16* p_x_lo     = (__nv_bfloat16*)sym_addr(g_x_lo);
    float* p_attfea = (float*)sym_addr(g_att_fea);
    float* p_WG     = (float*)sym_addr(g_WG);
    float* p_bcomb  = (float*)sym_addr(g_bcomb);
    float* p_h      = (float*)sym_addr(g_h);
    float* p_c      = (float*)sym_addr(g_c);
    float* p_gpart  = (float*)sym_addr(g_gpart);
    float* p_ahpart = (float*)sym_addr(g_ahpart);

    // ---- one-time conversions / packs ----
    split_kernel<<<(VV*DD + 255)/256, 256>>>(Wout, p_Wout_hi, p_Wout_lo, VV*DD);
    split_kernel<<<(BB*RR*VIS + 255)/256, 256>>>(visual, p_vis_hi, p_vis_lo, BB*RR*VIS);
    split_kernel<<<(ATT*VIS + 255)/256, 256>>>(Wv, p_Wv_hi, p_Wv_lo, ATT*VIS);
    pack_split_kernel<<<(G4*KCAT + 255)/256, 256>>>(Wih, Whh, bih, bhh);
    wihw_split_kernel<<<(G4*EE + 255)/256, 256>>>(Wih);
    words_split_kernel<<<(MW*EE + 255)/256, 256>>>(captions, embed_W);

    // h0 / c0 (fp32, M=128 N=1024 K=1024)
    gemm_f32<<<dim3(16, 2, 1), 256>>>(joint, W_init_h, b_init_h, p_h, BB, DD, MMD, MMD, MMD);
    gemm_f32<<<dim3(16, 2, 1), 256>>>(joint, W_init_c, b_init_c, p_c, BB, DD, MMD, MMD, MMD);
    h0_to_x_kernel<<<128, 1024>>>();

    // att_fea = visual @ Wv^T   (M=4608, N=512, K=2048)
    tgemm<0><<<dim3(4, 36, 1), 256>>>(
        p_vis_hi, p_vis_lo, p_Wv_hi, p_Wv_lo, nullptr, p_attfea,
        BB*RR, ATT, VIS, VIS, nullptr);
    // WG = words @ Wih_word^T + (bih+bhh)   (M=2432, N=4096, K=512)
    tgemm<0><<<dim3(32, 19, 1), 256>>>(
        p_words_hi, p_words_lo, p_WihW_hi, p_WihW_lo, p_bcomb, p_WG,
        MW, G4, EE, EE, nullptr);

    // ---- recurrence ----
    for (int t = 0; t < TT; t++) {
        // ah = h @ Wh^T split-K=4   (M=128, N=512, K=1024)
        gemm_f32<<<dim3(8, 2, 4), 256>>>(p_h, Wh, nullptr, p_ahpart, BB, ATT, DD, DD, DD/4);
        attn_kernel<<<BB, 256>>>(visual, att_bias, Ww, t);
        // gates partials = xcat @ [Wih_vis|Whh]^T, split-K=8 (M=128, N=4096, K=3072)
        tgemm<0><<<dim3(32, 1, NSPL), 256>>>(
            p_x_hi, p_x_lo, p_Wcat_hi, p_Wcat_lo, nullptr, p_gpart,
            BB, G4, KCAT, KCAT/NSPL, nullptr);
        lstm_kernel<<<128, 1024>>>(lengths, t);
    }

    // ---- batched vocab projection, masked epilogue (M=2432, N=10000, K=1024) ----
    tgemm<2><<<dim3(79, 19, 1), 256>>>(
        p_Hout_hi, p_Hout_lo, p_Wout_hi, p_Wout_lo, bout, out,
        MW, VV, DD, DD, lengths);

    (void)in_sizes; (void)n_in; (void)out_size;
}